// round 6
// baseline (speedup 1.0000x reference)
#include <cuda_runtime.h>
#include <cuda_bf16.h>

#define HID 20
#define NTHREADS 256
#define PTS_PER_THREAD 2

typedef unsigned long long u64;

// ---- shared-memory layout (float offsets) ----
#define OFF_FW   0        // front_W  [4][20]   80
#define OFF_FB   80       // front_b  [20]      20
#define OFF_BW   100      // back_W   [20][4]   80
#define OFF_BB   180      // back_b   [4]        4
#define OFF_WN1  184      // [16][3][20][20] 19200
#define OFF_BN1  19384    // [16][3][20]       960
#define OFF_WL1  20344    // [16][20][20]     6400
#define OFF_BL1  26744    // [16][20]          320
#define OFF_WN2  27064    // [4][3][20][20]   4800
#define OFF_BN2  31864    // [4][3][20]        240
#define OFF_WL2  32104    // [4][20][20]      1600
#define OFF_BL2  33704    // [4][20]            80
#define OFF_WN3  33784    // [1][3][20][20]   1200
#define OFF_BN3  34984    // [1][3][20]         60
#define OFF_WL3  35044    // [1][20][20]       400
#define OFF_BL3  35444    // [1][20]            20
#define SMEM_FLOATS 35464
#define SMEM_BYTES  (SMEM_FLOATS * 4)   // 141856

// ---- packed fp32x2 helpers ----
__device__ __forceinline__ u64 fma2(u64 a, u64 b, u64 c) {
    u64 d;
    asm("fma.rn.f32x2 %0, %1, %2, %3;" : "=l"(d) : "l"(a), "l"(b), "l"(c));
    return d;
}
__device__ __forceinline__ u64 pack2(float x, float y) {
    u64 r;
    asm("mov.b64 %0, {%1, %2};" : "=l"(r) : "f"(x), "f"(y));
    return r;
}
__device__ __forceinline__ void unpack2(u64 p, float& x, float& y) {
    asm("mov.b64 {%0, %1}, %2;" : "=f"(x), "=f"(y) : "l"(p));
}

// swish(x) = x*sigmoid(x) = hv + hv*tanh(hv), hv = x/2
__device__ __forceinline__ float swishf(float v) {
    float hv = 0.5f * v;
    float t;
    asm("tanh.approx.f32 %0, %1;" : "=f"(t) : "f"(hv));
    return fmaf(hv, t, hv);
}

__device__ __forceinline__ void smem_copy(float* dst, const float* src, int n,
                                          int tid, int nt) {
    for (int i = tid; i < n; i += nt) dst[i] = src[i];
}

// One 20x20 layer for TWO points -> packed pre-activation accumulators.
// FFMA2 emission order is ZIGZAG so every consecutive FFMA2 shares either the
// activation operand (a-slot) or the weight operand (b-slot) with its
// predecessor, enabling operand-reuse latches to cut RF bank reads from 3 to 2.
__device__ __forceinline__ void layer20x2(const float* __restrict__ o0,
                                          const float* __restrict__ o1,
                                          u64* __restrict__ acc0,
                                          u64* __restrict__ acc1,
                                          const float* __restrict__ W,
                                          const float* __restrict__ B) {
    const u64* Bp = reinterpret_cast<const u64*>(B);
#pragma unroll
    for (int q = 0; q < 10; ++q) {
        u64 b = Bp[q];
        acc0[q] = b;
        acc1[q] = b;
    }
#pragma unroll
    for (int i = 0; i < HID; ++i) {
        u64 a0 = pack2(o0[i], o0[i]);
        u64 a1 = pack2(o1[i], o1[i]);
        const float4* row = reinterpret_cast<const float4*>(W + i * HID);
#pragma unroll
        for (int q = 0; q < 5; ++q) {
            float4 w = row[q];
            u64 wlo = pack2(w.x, w.y);
            u64 whi = pack2(w.z, w.w);
            // zigzag: (a0,wlo) (a1,wlo) (a1,whi) (a0,whi)
            acc0[2 * q + 0] = fma2(a0, wlo, acc0[2 * q + 0]);
            acc1[2 * q + 0] = fma2(a1, wlo, acc1[2 * q + 0]);
            acc1[2 * q + 1] = fma2(a1, whi, acc1[2 * q + 1]);
            acc0[2 * q + 1] = fma2(a0, whi, acc0[2 * q + 1]);
        }
    }
}

// front: h = x @ front_W + front_b (scalar; tiny)
__device__ __forceinline__ void front(const float4& xv, float* __restrict__ h,
                                      const float* __restrict__ sm) {
#pragma unroll
    for (int k = 0; k < HID; ++k) {
        float a = sm[OFF_FB + k];
        a = fmaf(xv.x, sm[OFF_FW + 0 * HID + k], a);
        a = fmaf(xv.y, sm[OFF_FW + 1 * HID + k], a);
        a = fmaf(xv.z, sm[OFF_FW + 2 * HID + k], a);
        a = fmaf(xv.w, sm[OFF_FW + 3 * HID + k], a);
        h[k] = a;
    }
}

// Run one residual chain of L blocks over (h0, h1) in place.
__device__ __forceinline__ void run_chain2(float* __restrict__ h0,
                                           float* __restrict__ h1,
                                           const float* __restrict__ sWn,
                                           const float* __restrict__ sbn,
                                           const float* __restrict__ sWl,
                                           const float* __restrict__ sbl,
                                           int L) {
    for (int blk = 0; blk < L; ++blk) {
        float o0[HID], o1[HID];
#pragma unroll
        for (int k = 0; k < HID; ++k) { o0[k] = h0[k]; o1[k] = h1[k]; }

#pragma unroll
        for (int j = 0; j < 3; ++j) {
            const float* W = sWn + (blk * 3 + j) * (HID * HID);
            const float* B = sbn + (blk * 3 + j) * HID;
            u64 acc0[10], acc1[10];
            layer20x2(o0, o1, acc0, acc1, W, B);
#pragma unroll
            for (int q = 0; q < 10; ++q) {
                float a, b;
                unpack2(acc0[q], a, b);
                o0[2 * q] = swishf(a);
                o0[2 * q + 1] = swishf(b);
                unpack2(acc1[q], a, b);
                o1[2 * q] = swishf(a);
                o1[2 * q + 1] = swishf(b);
            }
        }
        // shortcut: h = o + swish(h @ Wl + bl)
        {
            const float* W = sWl + blk * (HID * HID);
            const float* B = sbl + blk * HID;
            u64 acc0[10], acc1[10];
            layer20x2(h0, h1, acc0, acc1, W, B);
#pragma unroll
            for (int q = 0; q < 10; ++q) {
                float a, b;
                unpack2(acc0[q], a, b);
                h0[2 * q] = o0[2 * q] + swishf(a);
                h0[2 * q + 1] = o0[2 * q + 1] + swishf(b);
                unpack2(acc1[q], a, b);
                h1[2 * q] = o1[2 * q] + swishf(a);
                h1[2 * q + 1] = o1[2 * q + 1] + swishf(b);
            }
        }
    }
}

__global__ void __launch_bounds__(NTHREADS, 1)
reslinear_kernel(const float* __restrict__ x,
                 const float* __restrict__ fW, const float* __restrict__ fB,
                 const float* __restrict__ bW, const float* __restrict__ bB,
                 const float* __restrict__ Wn1, const float* __restrict__ bn1,
                 const float* __restrict__ Wl1, const float* __restrict__ bl1,
                 const float* __restrict__ Wn2, const float* __restrict__ bn2,
                 const float* __restrict__ Wl2, const float* __restrict__ bl2,
                 const float* __restrict__ Wn3, const float* __restrict__ bn3,
                 const float* __restrict__ Wl3, const float* __restrict__ bl3,
                 float* __restrict__ out, int n) {
    extern __shared__ float sm[];
    const int tid = threadIdx.x;

    smem_copy(sm + OFF_FW, fW, 80, tid, NTHREADS);
    smem_copy(sm + OFF_FB, fB, 20, tid, NTHREADS);
    smem_copy(sm + OFF_BW, bW, 80, tid, NTHREADS);
    smem_copy(sm + OFF_BB, bB, 4, tid, NTHREADS);
    smem_copy(sm + OFF_WN1, Wn1, 19200, tid, NTHREADS);
    smem_copy(sm + OFF_BN1, bn1, 960, tid, NTHREADS);
    smem_copy(sm + OFF_WL1, Wl1, 6400, tid, NTHREADS);
    smem_copy(sm + OFF_BL1, bl1, 320, tid, NTHREADS);
    smem_copy(sm + OFF_WN2, Wn2, 4800, tid, NTHREADS);
    smem_copy(sm + OFF_BN2, bn2, 240, tid, NTHREADS);
    smem_copy(sm + OFF_WL2, Wl2, 1600, tid, NTHREADS);
    smem_copy(sm + OFF_BL2, bl2, 80, tid, NTHREADS);
    smem_copy(sm + OFF_WN3, Wn3, 1200, tid, NTHREADS);
    smem_copy(sm + OFF_BN3, bn3, 60, tid, NTHREADS);
    smem_copy(sm + OFF_WL3, Wl3, 400, tid, NTHREADS);
    smem_copy(sm + OFF_BL3, bl3, 20, tid, NTHREADS);
    __syncthreads();

    const int i0 = blockIdx.x * (NTHREADS * PTS_PER_THREAD) + tid;
    const int i1 = i0 + NTHREADS;
    if (i1 >= n) return;  // n is a multiple of 512; never trims real work

    const float4 xv0 = reinterpret_cast<const float4*>(x)[i0];
    const float4 xv1 = reinterpret_cast<const float4*>(x)[i1];

    float h0[HID], h1[HID];
    float s0[HID], s1[HID];

    // ---- chain 1 (L=16) ----
    front(xv0, h0, sm);
    front(xv1, h1, sm);
    run_chain2(h0, h1, sm + OFF_WN1, sm + OFF_BN1, sm + OFF_WL1, sm + OFF_BL1, 16);
#pragma unroll
    for (int k = 0; k < HID; ++k) { s0[k] = h0[k]; s1[k] = h1[k]; }

    // ---- chain 2 (L=4) ----
    front(xv0, h0, sm);
    front(xv1, h1, sm);
    run_chain2(h0, h1, sm + OFF_WN2, sm + OFF_BN2, sm + OFF_WL2, sm + OFF_BL2, 4);
#pragma unroll
    for (int k = 0; k < HID; ++k) { s0[k] += h0[k]; s1[k] += h1[k]; }

    // ---- chain 3 (L=1) ----
    front(xv0, h0, sm);
    front(xv1, h1, sm);
    run_chain2(h0, h1, sm + OFF_WN3, sm + OFF_BN3, sm + OFF_WL3, sm + OFF_BL3, 1);
#pragma unroll
    for (int k = 0; k < HID; ++k) { s0[k] += h0[k]; s1[k] += h1[k]; }

    // ---- back: out = s @ back_W + back_b   (back_W row-major [20][4]) ----
    float4 y0, y1;
    y0.x = y1.x = sm[OFF_BB + 0];
    y0.y = y1.y = sm[OFF_BB + 1];
    y0.z = y1.z = sm[OFF_BB + 2];
    y0.w = y1.w = sm[OFF_BB + 3];
#pragma unroll
    for (int k = 0; k < HID; ++k) {
        float w0 = sm[OFF_BW + k * 4 + 0];
        float w1 = sm[OFF_BW + k * 4 + 1];
        float w2 = sm[OFF_BW + k * 4 + 2];
        float w3 = sm[OFF_BW + k * 4 + 3];
        y0.x = fmaf(s0[k], w0, y0.x);
        y0.y = fmaf(s0[k], w1, y0.y);
        y0.z = fmaf(s0[k], w2, y0.z);
        y0.w = fmaf(s0[k], w3, y0.w);
        y1.x = fmaf(s1[k], w0, y1.x);
        y1.y = fmaf(s1[k], w1, y1.y);
        y1.z = fmaf(s1[k], w2, y1.z);
        y1.w = fmaf(s1[k], w3, y1.w);
    }
    reinterpret_cast<float4*>(out)[i0] = y0;
    reinterpret_cast<float4*>(out)[i1] = y1;
}

extern "C" void kernel_launch(void* const* d_in, const int* in_sizes, int n_in,
                              void* d_out, int out_size) {
    const float* x   = (const float*)d_in[0];
    const float* fW  = (const float*)d_in[1];
    const float* fB  = (const float*)d_in[2];
    const float* bW  = (const float*)d_in[3];
    const float* bB  = (const float*)d_in[4];
    const float* Wn1 = (const float*)d_in[5];
    const float* bn1 = (const float*)d_in[6];
    const float* Wl1 = (const float*)d_in[7];
    const float* bl1 = (const float*)d_in[8];
    const float* Wn2 = (const float*)d_in[9];
    const float* bn2 = (const float*)d_in[10];
    const float* Wl2 = (const float*)d_in[11];
    const float* bl2 = (const float*)d_in[12];
    const float* Wn3 = (const float*)d_in[13];
    const float* bn3 = (const float*)d_in[14];
    const float* Wl3 = (const float*)d_in[15];
    const float* bl3 = (const float*)d_in[16];
    float* out = (float*)d_out;

    const int n = in_sizes[0] / 4;

    cudaFuncSetAttribute(reslinear_kernel,
                         cudaFuncAttributeMaxDynamicSharedMemorySize, SMEM_BYTES);

    const int grid = (n + NTHREADS * PTS_PER_THREAD - 1) / (NTHREADS * PTS_PER_THREAD);
    reslinear_kernel<<<grid, NTHREADS, SMEM_BYTES>>>(
        x, fW, fB, bW, bB,
        Wn1, bn1, Wl1, bl1,
        Wn2, bn2, Wl2, bl2,
        Wn3, bn3, Wl3, bl3,
        out, n);
}

// round 7
// speedup vs baseline: 1.0009x; 1.0009x over previous
#include <cuda_runtime.h>
#include <cuda_bf16.h>

#define HID 20
#define NTHREADS 256
#define PTS_PER_THREAD 2

typedef unsigned long long u64;

// ---- shared-memory layout (float offsets) ----
#define OFF_FW   0        // front_W  [4][20]   80
#define OFF_FB   80       // front_b  [20]      20
#define OFF_BW   100      // back_W   [20][4]   80
#define OFF_BB   180      // back_b   [4]        4
#define OFF_WN1  184      // [16][3][20][20] 19200
#define OFF_BN1  19384    // [16][3][20]       960
#define OFF_WL1  20344    // [16][20][20]     6400
#define OFF_BL1  26744    // [16][20]          320
#define OFF_WN2  27064    // [4][3][20][20]   4800
#define OFF_BN2  31864    // [4][3][20]        240
#define OFF_WL2  32104    // [4][20][20]      1600
#define OFF_BL2  33704    // [4][20]            80
#define OFF_WN3  33784    // [1][3][20][20]   1200
#define OFF_BN3  34984    // [1][3][20]         60
#define OFF_WL3  35044    // [1][20][20]       400
#define OFF_BL3  35444    // [1][20]            20
#define SMEM_FLOATS 35464
#define SMEM_BYTES  (SMEM_FLOATS * 4)   // 141856

// ---- packed fp32x2 helpers ----
__device__ __forceinline__ u64 fma2(u64 a, u64 b, u64 c) {
    u64 d;
    asm("fma.rn.f32x2 %0, %1, %2, %3;" : "=l"(d) : "l"(a), "l"(b), "l"(c));
    return d;
}
__device__ __forceinline__ u64 pack2(float x, float y) {
    u64 r;
    asm("mov.b64 %0, {%1, %2};" : "=l"(r) : "f"(x), "f"(y));
    return r;
}
__device__ __forceinline__ void unpack2(u64 p, float& x, float& y) {
    asm("mov.b64 {%0, %1}, %2;" : "=f"(x), "=f"(y) : "l"(p));
}

// swish(x) = x*sigmoid(x) = hv + hv*tanh(hv), hv = x/2
__device__ __forceinline__ float swishf(float v) {
    float hv = 0.5f * v;
    float t;
    asm("tanh.approx.f32 %0, %1;" : "=f"(t) : "f"(hv));
    return fmaf(hv, t, hv);
}

__device__ __forceinline__ void smem_copy(float* dst, const float* src, int n,
                                          int tid, int nt) {
    for (int i = tid; i < n; i += nt) dst[i] = src[i];
}

// One 20x20 layer for TWO points -> packed pre-activation accumulators.
// FFMA2 emission order is ZIGZAG so every consecutive FFMA2 shares either the
// activation operand (a-slot) or the weight operand (b-slot) with its
// predecessor, enabling operand-reuse latches to cut RF bank reads from 3 to 2.
__device__ __forceinline__ void layer20x2(const float* __restrict__ o0,
                                          const float* __restrict__ o1,
                                          u64* __restrict__ acc0,
                                          u64* __restrict__ acc1,
                                          const float* __restrict__ W,
                                          const float* __restrict__ B) {
    const u64* Bp = reinterpret_cast<const u64*>(B);
#pragma unroll
    for (int q = 0; q < 10; ++q) {
        u64 b = Bp[q];
        acc0[q] = b;
        acc1[q] = b;
    }
#pragma unroll
    for (int i = 0; i < HID; ++i) {
        u64 a0 = pack2(o0[i], o0[i]);
        u64 a1 = pack2(o1[i], o1[i]);
        const float4* row = reinterpret_cast<const float4*>(W + i * HID);
#pragma unroll
        for (int q = 0; q < 5; ++q) {
            float4 w = row[q];
            u64 wlo = pack2(w.x, w.y);
            u64 whi = pack2(w.z, w.w);
            // zigzag: (a0,wlo) (a1,wlo) (a1,whi) (a0,whi)
            acc0[2 * q + 0] = fma2(a0, wlo, acc0[2 * q + 0]);
            acc1[2 * q + 0] = fma2(a1, wlo, acc1[2 * q + 0]);
            acc1[2 * q + 1] = fma2(a1, whi, acc1[2 * q + 1]);
            acc0[2 * q + 1] = fma2(a0, whi, acc0[2 * q + 1]);
        }
    }
}

// front: h = x @ front_W + front_b (scalar; tiny)
__device__ __forceinline__ void front(const float4& xv, float* __restrict__ h,
                                      const float* __restrict__ sm) {
#pragma unroll
    for (int k = 0; k < HID; ++k) {
        float a = sm[OFF_FB + k];
        a = fmaf(xv.x, sm[OFF_FW + 0 * HID + k], a);
        a = fmaf(xv.y, sm[OFF_FW + 1 * HID + k], a);
        a = fmaf(xv.z, sm[OFF_FW + 2 * HID + k], a);
        a = fmaf(xv.w, sm[OFF_FW + 3 * HID + k], a);
        h[k] = a;
    }
}

// Run one residual chain of L blocks over (h0, h1) in place.
__device__ __forceinline__ void run_chain2(float* __restrict__ h0,
                                           float* __restrict__ h1,
                                           const float* __restrict__ sWn,
                                           const float* __restrict__ sbn,
                                           const float* __restrict__ sWl,
                                           const float* __restrict__ sbl,
                                           int L) {
    for (int blk = 0; blk < L; ++blk) {
        float o0[HID], o1[HID];
#pragma unroll
        for (int k = 0; k < HID; ++k) { o0[k] = h0[k]; o1[k] = h1[k]; }

#pragma unroll
        for (int j = 0; j < 3; ++j) {
            const float* W = sWn + (blk * 3 + j) * (HID * HID);
            const float* B = sbn + (blk * 3 + j) * HID;
            u64 acc0[10], acc1[10];
            layer20x2(o0, o1, acc0, acc1, W, B);
#pragma unroll
            for (int q = 0; q < 10; ++q) {
                float a, b;
                unpack2(acc0[q], a, b);
                o0[2 * q] = swishf(a);
                o0[2 * q + 1] = swishf(b);
                unpack2(acc1[q], a, b);
                o1[2 * q] = swishf(a);
                o1[2 * q + 1] = swishf(b);
            }
        }
        // shortcut: h = o + swish(h @ Wl + bl)
        {
            const float* W = sWl + blk * (HID * HID);
            const float* B = sbl + blk * HID;
            u64 acc0[10], acc1[10];
            layer20x2(h0, h1, acc0, acc1, W, B);
#pragma unroll
            for (int q = 0; q < 10; ++q) {
                float a, b;
                unpack2(acc0[q], a, b);
                h0[2 * q] = o0[2 * q] + swishf(a);
                h0[2 * q + 1] = o0[2 * q + 1] + swishf(b);
                unpack2(acc1[q], a, b);
                h1[2 * q] = o1[2 * q] + swishf(a);
                h1[2 * q + 1] = o1[2 * q + 1] + swishf(b);
            }
        }
    }
}

__global__ void __launch_bounds__(NTHREADS, 1)
reslinear_kernel(const float* __restrict__ x,
                 const float* __restrict__ fW, const float* __restrict__ fB,
                 const float* __restrict__ bW, const float* __restrict__ bB,
                 const float* __restrict__ Wn1, const float* __restrict__ bn1,
                 const float* __restrict__ Wl1, const float* __restrict__ bl1,
                 const float* __restrict__ Wn2, const float* __restrict__ bn2,
                 const float* __restrict__ Wl2, const float* __restrict__ bl2,
                 const float* __restrict__ Wn3, const float* __restrict__ bn3,
                 const float* __restrict__ Wl3, const float* __restrict__ bl3,
                 float* __restrict__ out, int n) {
    extern __shared__ float sm[];
    const int tid = threadIdx.x;

    smem_copy(sm + OFF_FW, fW, 80, tid, NTHREADS);
    smem_copy(sm + OFF_FB, fB, 20, tid, NTHREADS);
    smem_copy(sm + OFF_BW, bW, 80, tid, NTHREADS);
    smem_copy(sm + OFF_BB, bB, 4, tid, NTHREADS);
    smem_copy(sm + OFF_WN1, Wn1, 19200, tid, NTHREADS);
    smem_copy(sm + OFF_BN1, bn1, 960, tid, NTHREADS);
    smem_copy(sm + OFF_WL1, Wl1, 6400, tid, NTHREADS);
    smem_copy(sm + OFF_BL1, bl1, 320, tid, NTHREADS);
    smem_copy(sm + OFF_WN2, Wn2, 4800, tid, NTHREADS);
    smem_copy(sm + OFF_BN2, bn2, 240, tid, NTHREADS);
    smem_copy(sm + OFF_WL2, Wl2, 1600, tid, NTHREADS);
    smem_copy(sm + OFF_BL2, bl2, 80, tid, NTHREADS);
    smem_copy(sm + OFF_WN3, Wn3, 1200, tid, NTHREADS);
    smem_copy(sm + OFF_BN3, bn3, 60, tid, NTHREADS);
    smem_copy(sm + OFF_WL3, Wl3, 400, tid, NTHREADS);
    smem_copy(sm + OFF_BL3, bl3, 20, tid, NTHREADS);
    __syncthreads();

    const int i0 = blockIdx.x * (NTHREADS * PTS_PER_THREAD) + tid;
    const int i1 = i0 + NTHREADS;
    if (i1 >= n) return;  // n is a multiple of 512; never trims real work

    const float4 xv0 = reinterpret_cast<const float4*>(x)[i0];
    const float4 xv1 = reinterpret_cast<const float4*>(x)[i1];

    float h0[HID], h1[HID];
    float s0[HID], s1[HID];

    // ---- chain 1 (L=16) ----
    front(xv0, h0, sm);
    front(xv1, h1, sm);
    run_chain2(h0, h1, sm + OFF_WN1, sm + OFF_BN1, sm + OFF_WL1, sm + OFF_BL1, 16);
#pragma unroll
    for (int k = 0; k < HID; ++k) { s0[k] = h0[k]; s1[k] = h1[k]; }

    // ---- chain 2 (L=4) ----
    front(xv0, h0, sm);
    front(xv1, h1, sm);
    run_chain2(h0, h1, sm + OFF_WN2, sm + OFF_BN2, sm + OFF_WL2, sm + OFF_BL2, 4);
#pragma unroll
    for (int k = 0; k < HID; ++k) { s0[k] += h0[k]; s1[k] += h1[k]; }

    // ---- chain 3 (L=1) ----
    front(xv0, h0, sm);
    front(xv1, h1, sm);
    run_chain2(h0, h1, sm + OFF_WN3, sm + OFF_BN3, sm + OFF_WL3, sm + OFF_BL3, 1);
#pragma unroll
    for (int k = 0; k < HID; ++k) { s0[k] += h0[k]; s1[k] += h1[k]; }

    // ---- back: out = s @ back_W + back_b   (back_W row-major [20][4]) ----
    float4 y0, y1;
    y0.x = y1.x = sm[OFF_BB + 0];
    y0.y = y1.y = sm[OFF_BB + 1];
    y0.z = y1.z = sm[OFF_BB + 2];
    y0.w = y1.w = sm[OFF_BB + 3];
#pragma unroll
    for (int k = 0; k < HID; ++k) {
        float w0 = sm[OFF_BW + k * 4 + 0];
        float w1 = sm[OFF_BW + k * 4 + 1];
        float w2 = sm[OFF_BW + k * 4 + 2];
        float w3 = sm[OFF_BW + k * 4 + 3];
        y0.x = fmaf(s0[k], w0, y0.x);
        y0.y = fmaf(s0[k], w1, y0.y);
        y0.z = fmaf(s0[k], w2, y0.z);
        y0.w = fmaf(s0[k], w3, y0.w);
        y1.x = fmaf(s1[k], w0, y1.x);
        y1.y = fmaf(s1[k], w1, y1.y);
        y1.z = fmaf(s1[k], w2, y1.z);
        y1.w = fmaf(s1[k], w3, y1.w);
    }
    reinterpret_cast<float4*>(out)[i0] = y0;
    reinterpret_cast<float4*>(out)[i1] = y1;
}

extern "C" void kernel_launch(void* const* d_in, const int* in_sizes, int n_in,
                              void* d_out, int out_size) {
    const float* x   = (const float*)d_in[0];
    const float* fW  = (const float*)d_in[1];
    const float* fB  = (const float*)d_in[2];
    const float* bW  = (const float*)d_in[3];
    const float* bB  = (const float*)d_in[4];
    const float* Wn1 = (const float*)d_in[5];
    const float* bn1 = (const float*)d_in[6];
    const float* Wl1 = (const float*)d_in[7];
    const float* bl1 = (const float*)d_in[8];
    const float* Wn2 = (const float*)d_in[9];
    const float* bn2 = (const float*)d_in[10];
    const float* Wl2 = (const float*)d_in[11];
    const float* bl2 = (const float*)d_in[12];
    const float* Wn3 = (const float*)d_in[13];
    const float* bn3 = (const float*)d_in[14];
    const float* Wl3 = (const float*)d_in[15];
    const float* bl3 = (const float*)d_in[16];
    float* out = (float*)d_out;

    const int n = in_sizes[0] / 4;

    cudaFuncSetAttribute(reslinear_kernel,
                         cudaFuncAttributeMaxDynamicSharedMemorySize, SMEM_BYTES);

    const int grid = (n + NTHREADS * PTS_PER_THREAD - 1) / (NTHREADS * PTS_PER_THREAD);
    reslinear_kernel<<<grid, NTHREADS, SMEM_BYTES>>>(
        x, fW, fB, bW, bB,
        Wn1, bn1, Wl1, bl1,
        Wn2, bn2, Wl2, bl2,
        Wn3, bn3, Wl3, bl3,
        out, n);
}

// round 8
// speedup vs baseline: 1.0016x; 1.0007x over previous
#include <cuda_runtime.h>
#include <cuda_bf16.h>

#define HID 20
#define NTHREADS 256
#define PTS_PER_THREAD 2

typedef unsigned long long u64;

// ---- shared-memory layout (float offsets) ----
#define OFF_FW   0        // front_W  [4][20]   80
#define OFF_FB   80       // front_b  [20]      20
#define OFF_BW   100      // back_W   [20][4]   80
#define OFF_BB   180      // back_b   [4]        4
#define OFF_WN1  184      // [16][3][20][20] 19200
#define OFF_BN1  19384    // [16][3][20]       960
#define OFF_WL1  20344    // [16][20][20]     6400
#define OFF_BL1  26744    // [16][20]          320
#define OFF_WN2  27064    // [4][3][20][20]   4800
#define OFF_BN2  31864    // [4][3][20]        240
#define OFF_WL2  32104    // [4][20][20]      1600
#define OFF_BL2  33704    // [4][20]            80
#define OFF_WN3  33784    // [1][3][20][20]   1200
#define OFF_BN3  34984    // [1][3][20]         60
#define OFF_WL3  35044    // [1][20][20]       400
#define OFF_BL3  35444    // [1][20]            20
#define SMEM_FLOATS 35464
#define SMEM_BYTES  (SMEM_FLOATS * 4)   // 141856

// ---- packed fp32x2 helpers ----
__device__ __forceinline__ u64 fma2(u64 a, u64 b, u64 c) {
    u64 d;
    asm("fma.rn.f32x2 %0, %1, %2, %3;" : "=l"(d) : "l"(a), "l"(b), "l"(c));
    return d;
}
__device__ __forceinline__ u64 pack2(float x, float y) {
    u64 r;
    asm("mov.b64 %0, {%1, %2};" : "=l"(r) : "f"(x), "f"(y));
    return r;
}
__device__ __forceinline__ void unpack2(u64 p, float& x, float& y) {
    asm("mov.b64 {%0, %1}, %2;" : "=f"(x), "=f"(y) : "l"(p));
}

// swish(x) = x*sigmoid(x) = hv + hv*tanh(hv), hv = x/2
__device__ __forceinline__ float swishf(float v) {
    float hv = 0.5f * v;
    float t;
    asm("tanh.approx.f32 %0, %1;" : "=f"(t) : "f"(hv));
    return fmaf(hv, t, hv);
}

__device__ __forceinline__ void smem_copy(float* dst, const float* src, int n,
                                          int tid, int nt) {
    for (int i = tid; i < n; i += nt) dst[i] = src[i];
}

// One 20x20 layer for TWO points -> packed pre-activation accumulators.
// FFMA2 emission order is ZIGZAG so every consecutive FFMA2 shares either the
// activation operand (a-slot) or the weight operand (b-slot) with its
// predecessor, enabling operand-reuse latches to cut RF bank reads from 3 to 2.
__device__ __forceinline__ void layer20x2(const float* __restrict__ o0,
                                          const float* __restrict__ o1,
                                          u64* __restrict__ acc0,
                                          u64* __restrict__ acc1,
                                          const float* __restrict__ W,
                                          const float* __restrict__ B) {
    const u64* Bp = reinterpret_cast<const u64*>(B);
#pragma unroll
    for (int q = 0; q < 10; ++q) {
        u64 b = Bp[q];
        acc0[q] = b;
        acc1[q] = b;
    }
#pragma unroll
    for (int i = 0; i < HID; ++i) {
        u64 a0 = pack2(o0[i], o0[i]);
        u64 a1 = pack2(o1[i], o1[i]);
        const float4* row = reinterpret_cast<const float4*>(W + i * HID);
#pragma unroll
        for (int q = 0; q < 5; ++q) {
            float4 w = row[q];
            u64 wlo = pack2(w.x, w.y);
            u64 whi = pack2(w.z, w.w);
            // zigzag: (a0,wlo) (a1,wlo) (a1,whi) (a0,whi)
            acc0[2 * q + 0] = fma2(a0, wlo, acc0[2 * q + 0]);
            acc1[2 * q + 0] = fma2(a1, wlo, acc1[2 * q + 0]);
            acc1[2 * q + 1] = fma2(a1, whi, acc1[2 * q + 1]);
            acc0[2 * q + 1] = fma2(a0, whi, acc0[2 * q + 1]);
        }
    }
}

// front: h = x @ front_W + front_b (scalar; tiny)
__device__ __forceinline__ void front(const float4& xv, float* __restrict__ h,
                                      const float* __restrict__ sm) {
#pragma unroll
    for (int k = 0; k < HID; ++k) {
        float a = sm[OFF_FB + k];
        a = fmaf(xv.x, sm[OFF_FW + 0 * HID + k], a);
        a = fmaf(xv.y, sm[OFF_FW + 1 * HID + k], a);
        a = fmaf(xv.z, sm[OFF_FW + 2 * HID + k], a);
        a = fmaf(xv.w, sm[OFF_FW + 3 * HID + k], a);
        h[k] = a;
    }
}

// Run one residual chain of L blocks over (h0, h1) in place.
__device__ __forceinline__ void run_chain2(float* __restrict__ h0,
                                           float* __restrict__ h1,
                                           const float* __restrict__ sWn,
                                           const float* __restrict__ sbn,
                                           const float* __restrict__ sWl,
                                           const float* __restrict__ sbl,
                                           int L) {
    for (int blk = 0; blk < L; ++blk) {
        float o0[HID], o1[HID];
#pragma unroll
        for (int k = 0; k < HID; ++k) { o0[k] = h0[k]; o1[k] = h1[k]; }

#pragma unroll
        for (int j = 0; j < 3; ++j) {
            const float* W = sWn + (blk * 3 + j) * (HID * HID);
            const float* B = sbn + (blk * 3 + j) * HID;
            u64 acc0[10], acc1[10];
            layer20x2(o0, o1, acc0, acc1, W, B);
#pragma unroll
            for (int q = 0; q < 10; ++q) {
                float a, b;
                unpack2(acc0[q], a, b);
                o0[2 * q] = swishf(a);
                o0[2 * q + 1] = swishf(b);
                unpack2(acc1[q], a, b);
                o1[2 * q] = swishf(a);
                o1[2 * q + 1] = swishf(b);
            }
        }
        // shortcut: h = o + swish(h @ Wl + bl)
        {
            const float* W = sWl + blk * (HID * HID);
            const float* B = sbl + blk * HID;
            u64 acc0[10], acc1[10];
            layer20x2(h0, h1, acc0, acc1, W, B);
#pragma unroll
            for (int q = 0; q < 10; ++q) {
                float a, b;
                unpack2(acc0[q], a, b);
                h0[2 * q] = o0[2 * q] + swishf(a);
                h0[2 * q + 1] = o0[2 * q + 1] + swishf(b);
                unpack2(acc1[q], a, b);
                h1[2 * q] = o1[2 * q] + swishf(a);
                h1[2 * q + 1] = o1[2 * q + 1] + swishf(b);
            }
        }
    }
}

__global__ void __launch_bounds__(NTHREADS, 1)
reslinear_kernel(const float* __restrict__ x,
                 const float* __restrict__ fW, const float* __restrict__ fB,
                 const float* __restrict__ bW, const float* __restrict__ bB,
                 const float* __restrict__ Wn1, const float* __restrict__ bn1,
                 const float* __restrict__ Wl1, const float* __restrict__ bl1,
                 const float* __restrict__ Wn2, const float* __restrict__ bn2,
                 const float* __restrict__ Wl2, const float* __restrict__ bl2,
                 const float* __restrict__ Wn3, const float* __restrict__ bn3,
                 const float* __restrict__ Wl3, const float* __restrict__ bl3,
                 float* __restrict__ out, int n) {
    extern __shared__ float sm[];
    const int tid = threadIdx.x;

    smem_copy(sm + OFF_FW, fW, 80, tid, NTHREADS);
    smem_copy(sm + OFF_FB, fB, 20, tid, NTHREADS);
    smem_copy(sm + OFF_BW, bW, 80, tid, NTHREADS);
    smem_copy(sm + OFF_BB, bB, 4, tid, NTHREADS);
    smem_copy(sm + OFF_WN1, Wn1, 19200, tid, NTHREADS);
    smem_copy(sm + OFF_BN1, bn1, 960, tid, NTHREADS);
    smem_copy(sm + OFF_WL1, Wl1, 6400, tid, NTHREADS);
    smem_copy(sm + OFF_BL1, bl1, 320, tid, NTHREADS);
    smem_copy(sm + OFF_WN2, Wn2, 4800, tid, NTHREADS);
    smem_copy(sm + OFF_BN2, bn2, 240, tid, NTHREADS);
    smem_copy(sm + OFF_WL2, Wl2, 1600, tid, NTHREADS);
    smem_copy(sm + OFF_BL2, bl2, 80, tid, NTHREADS);
    smem_copy(sm + OFF_WN3, Wn3, 1200, tid, NTHREADS);
    smem_copy(sm + OFF_BN3, bn3, 60, tid, NTHREADS);
    smem_copy(sm + OFF_WL3, Wl3, 400, tid, NTHREADS);
    smem_copy(sm + OFF_BL3, bl3, 20, tid, NTHREADS);
    __syncthreads();

    const int i0 = blockIdx.x * (NTHREADS * PTS_PER_THREAD) + tid;
    const int i1 = i0 + NTHREADS;
    if (i1 >= n) return;  // n is a multiple of 512; never trims real work

    const float4 xv0 = reinterpret_cast<const float4*>(x)[i0];
    const float4 xv1 = reinterpret_cast<const float4*>(x)[i1];

    float h0[HID], h1[HID];
    float s0[HID], s1[HID];

    // ---- chain 1 (L=16) ----
    front(xv0, h0, sm);
    front(xv1, h1, sm);
    run_chain2(h0, h1, sm + OFF_WN1, sm + OFF_BN1, sm + OFF_WL1, sm + OFF_BL1, 16);
#pragma unroll
    for (int k = 0; k < HID; ++k) { s0[k] = h0[k]; s1[k] = h1[k]; }

    // ---- chain 2 (L=4) ----
    front(xv0, h0, sm);
    front(xv1, h1, sm);
    run_chain2(h0, h1, sm + OFF_WN2, sm + OFF_BN2, sm + OFF_WL2, sm + OFF_BL2, 4);
#pragma unroll
    for (int k = 0; k < HID; ++k) { s0[k] += h0[k]; s1[k] += h1[k]; }

    // ---- chain 3 (L=1) ----
    front(xv0, h0, sm);
    front(xv1, h1, sm);
    run_chain2(h0, h1, sm + OFF_WN3, sm + OFF_BN3, sm + OFF_WL3, sm + OFF_BL3, 1);
#pragma unroll
    for (int k = 0; k < HID; ++k) { s0[k] += h0[k]; s1[k] += h1[k]; }

    // ---- back: out = s @ back_W + back_b   (back_W row-major [20][4]) ----
    float4 y0, y1;
    y0.x = y1.x = sm[OFF_BB + 0];
    y0.y = y1.y = sm[OFF_BB + 1];
    y0.z = y1.z = sm[OFF_BB + 2];
    y0.w = y1.w = sm[OFF_BB + 3];
#pragma unroll
    for (int k = 0; k < HID; ++k) {
        float w0 = sm[OFF_BW + k * 4 + 0];
        float w1 = sm[OFF_BW + k * 4 + 1];
        float w2 = sm[OFF_BW + k * 4 + 2];
        float w3 = sm[OFF_BW + k * 4 + 3];
        y0.x = fmaf(s0[k], w0, y0.x);
        y0.y = fmaf(s0[k], w1, y0.y);
        y0.z = fmaf(s0[k], w2, y0.z);
        y0.w = fmaf(s0[k], w3, y0.w);
        y1.x = fmaf(s1[k], w0, y1.x);
        y1.y = fmaf(s1[k], w1, y1.y);
        y1.z = fmaf(s1[k], w2, y1.z);
        y1.w = fmaf(s1[k], w3, y1.w);
    }
    reinterpret_cast<float4*>(out)[i0] = y0;
    reinterpret_cast<float4*>(out)[i1] = y1;
}

extern "C" void kernel_launch(void* const* d_in, const int* in_sizes, int n_in,
                              void* d_out, int out_size) {
    const float* x   = (const float*)d_in[0];
    const float* fW  = (const float*)d_in[1];
    const float* fB  = (const float*)d_in[2];
    const float* bW  = (const float*)d_in[3];
    const float* bB  = (const float*)d_in[4];
    const float* Wn1 = (const float*)d_in[5];
    const float* bn1 = (const float*)d_in[6];
    const float* Wl1 = (const float*)d_in[7];
    const float* bl1 = (const float*)d_in[8];
    const float* Wn2 = (const float*)d_in[9];
    const float* bn2 = (const float*)d_in[10];
    const float* Wl2 = (const float*)d_in[11];
    const float* bl2 = (const float*)d_in[12];
    const float* Wn3 = (const float*)d_in[13];
    const float* bn3 = (const float*)d_in[14];
    const float* Wl3 = (const float*)d_in[15];
    const float* bl3 = (const float*)d_in[16];
    float* out = (float*)d_out;

    const int n = in_sizes[0] / 4;

    cudaFuncSetAttribute(reslinear_kernel,
                         cudaFuncAttributeMaxDynamicSharedMemorySize, SMEM_BYTES);

    const int grid = (n + NTHREADS * PTS_PER_THREAD - 1) / (NTHREADS * PTS_PER_THREAD);
    reslinear_kernel<<<grid, NTHREADS, SMEM_BYTES>>>(
        x, fW, fB, bW, bB,
        Wn1, bn1, Wl1, bl1,
        Wn2, bn2, Wl2, bl2,
        Wn3, bn3, Wl3, bl3,
        out, n);
}

// round 9
// speedup vs baseline: 1.1548x; 1.1529x over previous
#include <cuda_runtime.h>
#include <cuda_fp16.h>
#include <cuda_bf16.h>

#define NT 256
typedef unsigned int u32;

// ---- shared memory layout (float-index offsets) ----
#define OFF_BF   0          // u32[84*9*32] = 24192 B-fragment words
#define OFF_BIAS 24192      // f32[84*24]  = 2016 (zero-padded to 24 cols)
#define OFF_H    26208      // f32[24][256] front activations / reused for s
#define OFF_FR   32352      // f32[100] front_W[4][20] + front_b[20]
#define OFF_BK   32452      // f32[84]  back_W[20][4] + back_b[4]
#define SMEM_FLOATS 32536
#define SMEM_BYTES (SMEM_FLOATS * 4)   // 130144

// pack two f32 -> f16x2 (lo = first arg)
__device__ __forceinline__ u32 packh2(float lo, float hi) {
    u32 r;
    asm("cvt.rn.f16x2.f32 %0, %1, %2;" : "=r"(r) : "f"(hi), "f"(lo));
    return r;
}

// swish(x) = hv + hv*tanh(hv), hv = x/2 ; swish(0) == 0 exactly (pad-safe)
__device__ __forceinline__ float swishf(float v) {
    float hv = 0.5f * v;
    float t;
    asm("tanh.approx.f32 %0, %1;" : "=f"(t) : "f"(hv));
    return fmaf(hv, t, hv);
}

// D(f32,m16n8) += A(f16,m16k8) * B(f16,k8n8)
__device__ __forceinline__ void mma8(float* d, u32 a0, u32 a1, u32 b) {
    asm volatile(
        "mma.sync.aligned.m16n8k8.row.col.f32.f16.f16.f32 "
        "{%0,%1,%2,%3}, {%4,%5}, {%6}, {%0,%1,%2,%3};"
        : "+f"(d[0]), "+f"(d[1]), "+f"(d[2]), "+f"(d[3])
        : "r"(a0), "r"(a1), "r"(b));
}

__global__ void __launch_bounds__(NT, 1)
reslinear_kernel(const float* __restrict__ x,
                 const float* __restrict__ fW, const float* __restrict__ fB,
                 const float* __restrict__ bW, const float* __restrict__ bB,
                 const float* __restrict__ Wn1, const float* __restrict__ bn1,
                 const float* __restrict__ Wl1, const float* __restrict__ bl1,
                 const float* __restrict__ Wn2, const float* __restrict__ bn2,
                 const float* __restrict__ Wl2, const float* __restrict__ bl2,
                 const float* __restrict__ Wn3, const float* __restrict__ bn3,
                 const float* __restrict__ Wl3, const float* __restrict__ bl3,
                 float* __restrict__ out, int n) {
    extern __shared__ float sm[];
    const int tid = threadIdx.x;
    u32* bfw = reinterpret_cast<u32*>(sm + OFF_BF);

    // ---- stage small params ----
    for (int w = tid; w < 80; w += NT) sm[OFF_FR + w] = fW[w];
    for (int w = tid; w < 20; w += NT) sm[OFF_FR + 80 + w] = fB[w];
    for (int w = tid; w < 80; w += NT) sm[OFF_BK + w] = bW[w];
    for (int w = tid; w < 4;  w += NT) sm[OFF_BK + 80 + w] = bB[w];

    // ---- pre-pack all 84 layer weights into mma B-fragment order (fp16) ----
    // layer L = gb*4 + j ; gb: 0-15 chain1, 16-19 chain2, 20 chain3 ; j: 0-2 net, 3 shortcut
    for (int w = tid; w < 24192; w += NT) {
        const int lane = w & 31;
        const int t9 = (w >> 5) % 9;
        const int L = w / 288;
        const int gb = L >> 2, j = L & 3;
        const float* W;
        if (gb < 16)      W = (j < 3) ? Wn1 + (gb * 3 + j) * 400 : Wl1 + gb * 400;
        else if (gb < 20) W = (j < 3) ? Wn2 + ((gb - 16) * 3 + j) * 400 : Wl2 + (gb - 16) * 400;
        else              W = (j < 3) ? Wn3 + j * 400 : Wl3;
        const int ks = t9 / 3, ns = t9 % 3;
        const int k0 = ks * 8 + (lane & 3) * 2;
        const int nn = ns * 8 + (lane >> 2);
        float lo = (k0     < 20 && nn < 20) ? W[k0 * 20 + nn]       : 0.f;
        float hi = (k0 + 1 < 20 && nn < 20) ? W[(k0 + 1) * 20 + nn] : 0.f;
        bfw[w] = packh2(lo, hi);
    }
    for (int w = tid; w < 2016; w += NT) {
        const int L = w / 24, nn = w % 24;
        const int gb = L >> 2, j = L & 3;
        const float* B;
        if (gb < 16)      B = (j < 3) ? bn1 + (gb * 3 + j) * 20 : bl1 + gb * 20;
        else if (gb < 20) B = (j < 3) ? bn2 + ((gb - 16) * 3 + j) * 20 : bl2 + (gb - 16) * 20;
        else              B = (j < 3) ? bn3 + j * 20 : bl3;
        sm[OFF_BIAS + w] = (nn < 20) ? B[nn] : 0.f;
    }
    __syncthreads();

    // ---- front layer: h = x @ fW + fb into H[24][256] (pad rows zero) ----
    {
        const float4 xv = reinterpret_cast<const float4*>(x)[blockIdx.x * NT + tid];
#pragma unroll
        for (int k = 0; k < 24; ++k) {
            float a = 0.f;
            if (k < 20) {
                a = sm[OFF_FR + 80 + k];
                a = fmaf(xv.x, sm[OFF_FR + 0 * 20 + k], a);
                a = fmaf(xv.y, sm[OFF_FR + 1 * 20 + k], a);
                a = fmaf(xv.z, sm[OFF_FR + 2 * 20 + k], a);
                a = fmaf(xv.w, sm[OFF_FR + 3 * 20 + k], a);
            }
            sm[OFF_H + k * NT + tid] = a;
        }
    }
    __syncthreads();

    const int lane = tid & 31, warp = tid >> 5;
    const int grp = lane >> 2, tq = lane & 3;
    const int p0 = warp * 32 + grp;        // tile0 base point (local)
    const int p1 = p0 + 16;                // tile1
    float* H = sm + OFF_H;
    const float* BIAS = sm + OFF_BIAS;

    float s[2][3][4];   // cross-chain accumulator, D-fragment layout

#pragma unroll
    for (int c = 0; c < 3; ++c) {
        // load h fragments from H (fragment-identity: A m16k8 == D m16n8 layout)
        u32 af[2][3][2];
#pragma unroll
        for (int t = 0; t < 2; ++t) {
            const int pb = t ? p1 : p0;
#pragma unroll
            for (int ks = 0; ks < 3; ++ks) {
                const int kk = ks * 8 + tq * 2;
                af[t][ks][0] = packh2(H[kk * NT + pb],     H[(kk + 1) * NT + pb]);
                af[t][ks][1] = packh2(H[kk * NT + pb + 8], H[(kk + 1) * NT + pb + 8]);
            }
        }
        const int b0 = (c == 0) ? 0 : (c == 1) ? 16 : 20;
        const int nb = (c == 0) ? 16 : (c == 1) ? 4 : 1;

        for (int blk = 0; blk < nb; ++blk) {
            const int Lb = (b0 + blk) * 4;
            u32 cur[2][3][2];
#pragma unroll
            for (int t = 0; t < 2; ++t)
#pragma unroll
                for (int ks = 0; ks < 3; ++ks) {
                    cur[t][ks][0] = af[t][ks][0];
                    cur[t][ks][1] = af[t][ks][1];
                }
            float o3[2][3][4];

            // ---- 3 net layers ----
#pragma unroll
            for (int j = 0; j < 3; ++j) {
                const int L = Lb + j;
                u32 bf[9];
#pragma unroll
                for (int t9 = 0; t9 < 9; ++t9) bf[t9] = bfw[(L * 9 + t9) * 32 + lane];
                float2 bp[3];
#pragma unroll
                for (int ns = 0; ns < 3; ++ns)
                    bp[ns] = *reinterpret_cast<const float2*>(BIAS + L * 24 + ns * 8 + tq * 2);
#pragma unroll
                for (int t = 0; t < 2; ++t) {
                    float D[3][4];
#pragma unroll
                    for (int ns = 0; ns < 3; ++ns) {
                        D[ns][0] = bp[ns].x; D[ns][1] = bp[ns].y;
                        D[ns][2] = bp[ns].x; D[ns][3] = bp[ns].y;
                    }
#pragma unroll
                    for (int ks = 0; ks < 3; ++ks)
#pragma unroll
                        for (int ns = 0; ns < 3; ++ns)
                            mma8(D[ns], cur[t][ks][0], cur[t][ks][1], bf[ks * 3 + ns]);
                    if (j < 2) {
#pragma unroll
                        for (int ns = 0; ns < 3; ++ns) {
                            cur[t][ns][0] = packh2(swishf(D[ns][0]), swishf(D[ns][1]));
                            cur[t][ns][1] = packh2(swishf(D[ns][2]), swishf(D[ns][3]));
                        }
                    } else {
#pragma unroll
                        for (int ns = 0; ns < 3; ++ns)
#pragma unroll
                            for (int i = 0; i < 4; ++i) o3[t][ns][i] = swishf(D[ns][i]);
                    }
                }
            }

            // ---- shortcut + residual: h' = o3 + swish(h @ Wl + bl) ----
            {
                const int L = Lb + 3;
                u32 bf[9];
#pragma unroll
                for (int t9 = 0; t9 < 9; ++t9) bf[t9] = bfw[(L * 9 + t9) * 32 + lane];
                float2 bp[3];
#pragma unroll
                for (int ns = 0; ns < 3; ++ns)
                    bp[ns] = *reinterpret_cast<const float2*>(BIAS + L * 24 + ns * 8 + tq * 2);
#pragma unroll
                for (int t = 0; t < 2; ++t) {
                    float D[3][4];
#pragma unroll
                    for (int ns = 0; ns < 3; ++ns) {
                        D[ns][0] = bp[ns].x; D[ns][1] = bp[ns].y;
                        D[ns][2] = bp[ns].x; D[ns][3] = bp[ns].y;
                    }
#pragma unroll
                    for (int ks = 0; ks < 3; ++ks)
#pragma unroll
                        for (int ns = 0; ns < 3; ++ns)
                            mma8(D[ns], af[t][ks][0], af[t][ks][1], bf[ks * 3 + ns]);
                    float hp[3][4];
#pragma unroll
                    for (int ns = 0; ns < 3; ++ns)
#pragma unroll
                        for (int i = 0; i < 4; ++i)
                            hp[ns][i] = o3[t][ns][i] + swishf(D[ns][i]);
#pragma unroll
                    for (int ns = 0; ns < 3; ++ns) {
                        af[t][ns][0] = packh2(hp[ns][0], hp[ns][1]);
                        af[t][ns][1] = packh2(hp[ns][2], hp[ns][3]);
                    }
                    if (blk == nb - 1) {
                        if (c == 0) {
#pragma unroll
                            for (int ns = 0; ns < 3; ++ns)
#pragma unroll
                                for (int i = 0; i < 4; ++i) s[t][ns][i] = hp[ns][i];
                        } else {
#pragma unroll
                            for (int ns = 0; ns < 3; ++ns)
#pragma unroll
                                for (int i = 0; i < 4; ++i) s[t][ns][i] += hp[ns][i];
                        }
                    }
                }
            }
        }
    }

    // ---- back layer: scatter s (D-layout) into H, then per-thread dot ----
#pragma unroll
    for (int t = 0; t < 2; ++t) {
        const int pb = t ? p1 : p0;
#pragma unroll
        for (int ns = 0; ns < 3; ++ns) {
            const int col = ns * 8 + tq * 2;
            H[col * NT + pb]           = s[t][ns][0];
            H[(col + 1) * NT + pb]     = s[t][ns][1];
            H[col * NT + pb + 8]       = s[t][ns][2];
            H[(col + 1) * NT + pb + 8] = s[t][ns][3];
        }
    }
    __syncwarp();

    float4 y;
    y.x = sm[OFF_BK + 80];
    y.y = sm[OFF_BK + 81];
    y.z = sm[OFF_BK + 82];
    y.w = sm[OFF_BK + 83];
#pragma unroll
    for (int k = 0; k < 20; ++k) {
        const float sk = H[k * NT + tid];
        y.x = fmaf(sk, sm[OFF_BK + k * 4 + 0], y.x);
        y.y = fmaf(sk, sm[OFF_BK + k * 4 + 1], y.y);
        y.z = fmaf(sk, sm[OFF_BK + k * 4 + 2], y.z);
        y.w = fmaf(sk, sm[OFF_BK + k * 4 + 3], y.w);
    }
    reinterpret_cast<float4*>(out)[blockIdx.x * NT + tid] = y;
}

extern "C" void kernel_launch(void* const* d_in, const int* in_sizes, int n_in,
                              void* d_out, int out_size) {
    const float* x   = (const float*)d_in[0];
    const float* fW  = (const float*)d_in[1];
    const float* fB  = (const float*)d_in[2];
    const float* bW  = (const float*)d_in[3];
    const float* bB  = (const float*)d_in[4];
    const float* Wn1 = (const float*)d_in[5];
    const float* bn1 = (const float*)d_in[6];
    const float* Wl1 = (const float*)d_in[7];
    const float* bl1 = (const float*)d_in[8];
    const float* Wn2 = (const float*)d_in[9];
    const float* bn2 = (const float*)d_in[10];
    const float* Wl2 = (const float*)d_in[11];
    const float* bl2 = (const float*)d_in[12];
    const float* Wn3 = (const float*)d_in[13];
    const float* bn3 = (const float*)d_in[14];
    const float* Wl3 = (const float*)d_in[15];
    const float* bl3 = (const float*)d_in[16];
    float* out = (float*)d_out;

    const int n = in_sizes[0] / 4;

    cudaFuncSetAttribute(reslinear_kernel,
                         cudaFuncAttributeMaxDynamicSharedMemorySize, SMEM_BYTES);

    const int grid = n / NT;   // N = 2^21, divisible by 256
    reslinear_kernel<<<grid, NT, SMEM_BYTES>>>(
        x, fW, fB, bW, bB,
        Wn1, bn1, Wl1, bl1,
        Wn2, bn2, Wl2, bl2,
        Wn3, bn3, Wl3, bl3,
        out, n);
}

// round 10
// speedup vs baseline: 1.6109x; 1.3950x over previous
#include <cuda_runtime.h>
#include <cuda_fp16.h>
#include <cuda_bf16.h>

#define NT 384
typedef unsigned int u32;

// ---- shared memory layout (float-index offsets) ----
#define OFF_BF   0          // u32[84*9*32] = 24192 B-fragment words
#define OFF_BIAS 24192      // f32[84*24]  = 2016 (zero-padded to 24 cols)
#define OFF_H    26208      // f32[24][NT] front activations / reused for s
#define OFF_FR   (26208 + 24 * NT)            // f32[100]
#define OFF_BK   (26208 + 24 * NT + 100)      // f32[84]
#define SMEM_FLOATS (26208 + 24 * NT + 184)
#define SMEM_BYTES (SMEM_FLOATS * 4)          // 142432 @ NT=384

// pack two f32 -> f16x2 (lo = first arg -> .lo half)
__device__ __forceinline__ u32 packh2(float lo, float hi) {
    u32 r;
    asm("cvt.rn.f16x2.f32 %0, %1, %2;" : "=r"(r) : "f"(hi), "f"(lo));
    return r;
}

// half2 swish on a packed f16x2: hv = v/2 ; r = hv + hv*tanh(hv)
__device__ __forceinline__ u32 hswish2(u32 v) {
    u32 hv, t, r;
    asm("mul.rn.f16x2 %0, %1, %2;" : "=r"(hv) : "r"(v), "r"(0x38003800u));
    asm("tanh.approx.f16x2 %0, %1;" : "=r"(t) : "r"(hv));
    asm("fma.rn.f16x2 %0, %1, %2, %3;" : "=r"(r) : "r"(hv), "r"(t), "r"(hv));
    return r;
}
__device__ __forceinline__ u32 hadd2(u32 a, u32 b) {
    u32 r;
    asm("add.rn.f16x2 %0, %1, %2;" : "=r"(r) : "r"(a), "r"(b));
    return r;
}
__device__ __forceinline__ void h2f2(u32 v, float& lo, float& hi) {
    __half2 h = *reinterpret_cast<__half2*>(&v);
    float2 f = __half22float2(h);
    lo = f.x; hi = f.y;
}

// D(f32,m16n8) += A(f16,m16k8) * B(f16,k8n8)
__device__ __forceinline__ void mma8(float* d, u32 a0, u32 a1, u32 b) {
    asm volatile(
        "mma.sync.aligned.m16n8k8.row.col.f32.f16.f16.f32 "
        "{%0,%1,%2,%3}, {%4,%5}, {%6}, {%0,%1,%2,%3};"
        : "+f"(d[0]), "+f"(d[1]), "+f"(d[2]), "+f"(d[3])
        : "r"(a0), "r"(a1), "r"(b));
}

__global__ void __launch_bounds__(NT, 1)
reslinear_kernel(const float* __restrict__ x,
                 const float* __restrict__ fW, const float* __restrict__ fB,
                 const float* __restrict__ bW, const float* __restrict__ bB,
                 const float* __restrict__ Wn1, const float* __restrict__ bn1,
                 const float* __restrict__ Wl1, const float* __restrict__ bl1,
                 const float* __restrict__ Wn2, const float* __restrict__ bn2,
                 const float* __restrict__ Wl2, const float* __restrict__ bl2,
                 const float* __restrict__ Wn3, const float* __restrict__ bn3,
                 const float* __restrict__ Wl3, const float* __restrict__ bl3,
                 float* __restrict__ out, int n) {
    extern __shared__ float sm[];
    const int tid = threadIdx.x;
    u32* bfw = reinterpret_cast<u32*>(sm + OFF_BF);

    // ---- stage small params ----
    for (int w = tid; w < 80; w += NT) sm[OFF_FR + w] = fW[w];
    for (int w = tid; w < 20; w += NT) sm[OFF_FR + 80 + w] = fB[w];
    for (int w = tid; w < 80; w += NT) sm[OFF_BK + w] = bW[w];
    for (int w = tid; w < 4;  w += NT) sm[OFF_BK + 80 + w] = bB[w];

    // ---- pre-pack all 84 layer weights into mma B-fragment order (fp16) ----
    for (int w = tid; w < 24192; w += NT) {
        const int lane = w & 31;
        const int t9 = (w >> 5) % 9;
        const int L = w / 288;
        const int gb = L >> 2, j = L & 3;
        const float* W;
        if (gb < 16)      W = (j < 3) ? Wn1 + (gb * 3 + j) * 400 : Wl1 + gb * 400;
        else if (gb < 20) W = (j < 3) ? Wn2 + ((gb - 16) * 3 + j) * 400 : Wl2 + (gb - 16) * 400;
        else              W = (j < 3) ? Wn3 + j * 400 : Wl3;
        const int ks = t9 / 3, ns = t9 % 3;
        const int k0 = ks * 8 + (lane & 3) * 2;
        const int nn = ns * 8 + (lane >> 2);
        float lo = (k0     < 20 && nn < 20) ? W[k0 * 20 + nn]       : 0.f;
        float hi = (k0 + 1 < 20 && nn < 20) ? W[(k0 + 1) * 20 + nn] : 0.f;
        bfw[w] = packh2(lo, hi);
    }
    for (int w = tid; w < 2016; w += NT) {
        const int L = w / 24, nn = w % 24;
        const int gb = L >> 2, j = L & 3;
        const float* B;
        if (gb < 16)      B = (j < 3) ? bn1 + (gb * 3 + j) * 20 : bl1 + gb * 20;
        else if (gb < 20) B = (j < 3) ? bn2 + ((gb - 16) * 3 + j) * 20 : bl2 + (gb - 16) * 20;
        else              B = (j < 3) ? bn3 + j * 20 : bl3;
        sm[OFF_BIAS + w] = (nn < 20) ? B[nn] : 0.f;
    }
    __syncthreads();

    const int gidx = blockIdx.x * NT + tid;
    const int lidx = (gidx < n) ? gidx : (n - 1);

    // ---- front layer: h = x @ fW + fb into H[24][NT] (pad rows zero) ----
    {
        const float4 xv = reinterpret_cast<const float4*>(x)[lidx];
#pragma unroll
        for (int k = 0; k < 24; ++k) {
            float a = 0.f;
            if (k < 20) {
                a = sm[OFF_FR + 80 + k];
                a = fmaf(xv.x, sm[OFF_FR + 0 * 20 + k], a);
                a = fmaf(xv.y, sm[OFF_FR + 1 * 20 + k], a);
                a = fmaf(xv.z, sm[OFF_FR + 2 * 20 + k], a);
                a = fmaf(xv.w, sm[OFF_FR + 3 * 20 + k], a);
            }
            sm[OFF_H + k * NT + tid] = a;
        }
    }
    __syncthreads();

    const int lane = tid & 31, warp = tid >> 5;
    const int grp = lane >> 2, tq = lane & 3;
    const int p0 = warp * 32 + grp;        // tile0 base point (local)
    const int p1 = p0 + 16;                // tile1
    float* H = sm + OFF_H;
    const float* BIAS = sm + OFF_BIAS;

    float s[2][3][4];   // cross-chain accumulator, D-fragment layout (f32)

#pragma unroll
    for (int c = 0; c < 3; ++c) {
        // load h fragments from H (fragment-identity: A m16k8 == D m16n8 layout)
        u32 af[2][3][2];
#pragma unroll
        for (int t = 0; t < 2; ++t) {
            const int pb = t ? p1 : p0;
#pragma unroll
            for (int ks = 0; ks < 3; ++ks) {
                const int kk = ks * 8 + tq * 2;
                af[t][ks][0] = packh2(H[kk * NT + pb],     H[(kk + 1) * NT + pb]);
                af[t][ks][1] = packh2(H[kk * NT + pb + 8], H[(kk + 1) * NT + pb + 8]);
            }
        }
        const int b0 = (c == 0) ? 0 : (c == 1) ? 16 : 20;
        const int nb = (c == 0) ? 16 : (c == 1) ? 4 : 1;

        for (int blk = 0; blk < nb; ++blk) {
            const int Lb = (b0 + blk) * 4;
            u32 cur[2][3][2];
#pragma unroll
            for (int t = 0; t < 2; ++t)
#pragma unroll
                for (int ks = 0; ks < 3; ++ks) {
                    cur[t][ks][0] = af[t][ks][0];
                    cur[t][ks][1] = af[t][ks][1];
                }
            u32 o3h[2][3][2];   // layer-3 output, f16x2 fragments

            // ---- 3 net layers ----
#pragma unroll
            for (int j = 0; j < 3; ++j) {
                const int L = Lb + j;
                u32 bf[9];
#pragma unroll
                for (int t9 = 0; t9 < 9; ++t9) bf[t9] = bfw[(L * 9 + t9) * 32 + lane];
                float2 bp[3];
#pragma unroll
                for (int ns = 0; ns < 3; ++ns)
                    bp[ns] = *reinterpret_cast<const float2*>(BIAS + L * 24 + ns * 8 + tq * 2);
#pragma unroll
                for (int t = 0; t < 2; ++t) {
                    float D[3][4];
#pragma unroll
                    for (int ns = 0; ns < 3; ++ns) {
                        D[ns][0] = bp[ns].x; D[ns][1] = bp[ns].y;
                        D[ns][2] = bp[ns].x; D[ns][3] = bp[ns].y;
                    }
#pragma unroll
                    for (int ks = 0; ks < 3; ++ks)
#pragma unroll
                        for (int ns = 0; ns < 3; ++ns)
                            mma8(D[ns], cur[t][ks][0], cur[t][ks][1], bf[ks * 3 + ns]);
#pragma unroll
                    for (int ns = 0; ns < 3; ++ns) {
                        u32 a = hswish2(packh2(D[ns][0], D[ns][1]));
                        u32 b = hswish2(packh2(D[ns][2], D[ns][3]));
                        if (j < 2) { cur[t][ns][0] = a; cur[t][ns][1] = b; }
                        else       { o3h[t][ns][0] = a; o3h[t][ns][1] = b; }
                    }
                }
            }

            // ---- shortcut + residual: h' = o3 + swish(h @ Wl + bl) ----
            {
                const int L = Lb + 3;
                u32 bf[9];
#pragma unroll
                for (int t9 = 0; t9 < 9; ++t9) bf[t9] = bfw[(L * 9 + t9) * 32 + lane];
                float2 bp[3];
#pragma unroll
                for (int ns = 0; ns < 3; ++ns)
                    bp[ns] = *reinterpret_cast<const float2*>(BIAS + L * 24 + ns * 8 + tq * 2);
#pragma unroll
                for (int t = 0; t < 2; ++t) {
                    float D[3][4];
#pragma unroll
                    for (int ns = 0; ns < 3; ++ns) {
                        D[ns][0] = bp[ns].x; D[ns][1] = bp[ns].y;
                        D[ns][2] = bp[ns].x; D[ns][3] = bp[ns].y;
                    }
#pragma unroll
                    for (int ks = 0; ks < 3; ++ks)
#pragma unroll
                        for (int ns = 0; ns < 3; ++ns)
                            mma8(D[ns], af[t][ks][0], af[t][ks][1], bf[ks * 3 + ns]);
#pragma unroll
                    for (int ns = 0; ns < 3; ++ns) {
                        u32 hp0 = hadd2(o3h[t][ns][0], hswish2(packh2(D[ns][0], D[ns][1])));
                        u32 hp1 = hadd2(o3h[t][ns][1], hswish2(packh2(D[ns][2], D[ns][3])));
                        af[t][ns][0] = hp0;
                        af[t][ns][1] = hp1;
                        if (blk == nb - 1) {
                            float f0, f1, f2, f3;
                            h2f2(hp0, f0, f1);
                            h2f2(hp1, f2, f3);
                            if (c == 0) {
                                s[t][ns][0] = f0; s[t][ns][1] = f1;
                                s[t][ns][2] = f2; s[t][ns][3] = f3;
                            } else {
                                s[t][ns][0] += f0; s[t][ns][1] += f1;
                                s[t][ns][2] += f2; s[t][ns][3] += f3;
                            }
                        }
                    }
                }
            }
        }
    }

    // ---- back layer: scatter s (D-layout) into H, then per-thread dot ----
#pragma unroll
    for (int t = 0; t < 2; ++t) {
        const int pb = t ? p1 : p0;
#pragma unroll
        for (int ns = 0; ns < 3; ++ns) {
            const int col = ns * 8 + tq * 2;
            H[col * NT + pb]           = s[t][ns][0];
            H[(col + 1) * NT + pb]     = s[t][ns][1];
            H[col * NT + pb + 8]       = s[t][ns][2];
            H[(col + 1) * NT + pb + 8] = s[t][ns][3];
        }
    }
    __syncwarp();

    float4 y;
    y.x = sm[OFF_BK + 80];
    y.y = sm[OFF_BK + 81];
    y.z = sm[OFF_BK + 82];
    y.w = sm[OFF_BK + 83];
#pragma unroll
    for (int k = 0; k < 20; ++k) {
        const float sk = H[k * NT + tid];
        y.x = fmaf(sk, sm[OFF_BK + k * 4 + 0], y.x);
        y.y = fmaf(sk, sm[OFF_BK + k * 4 + 1], y.y);
        y.z = fmaf(sk, sm[OFF_BK + k * 4 + 2], y.z);
        y.w = fmaf(sk, sm[OFF_BK + k * 4 + 3], y.w);
    }
    if (gidx < n) reinterpret_cast<float4*>(out)[gidx] = y;
}

extern "C" void kernel_launch(void* const* d_in, const int* in_sizes, int n_in,
                              void* d_out, int out_size) {
    const float* x   = (const float*)d_in[0];
    const float* fW  = (const float*)d_in[1];
    const float* fB  = (const float*)d_in[2];
    const float* bW  = (const float*)d_in[3];
    const float* bB  = (const float*)d_in[4];
    const float* Wn1 = (const float*)d_in[5];
    const float* bn1 = (const float*)d_in[6];
    const float* Wl1 = (const float*)d_in[7];
    const float* bl1 = (const float*)d_in[8];
    const float* Wn2 = (const float*)d_in[9];
    const float* bn2 = (const float*)d_in[10];
    const float* Wl2 = (const float*)d_in[11];
    const float* bl2 = (const float*)d_in[12];
    const float* Wn3 = (const float*)d_in[13];
    const float* bn3 = (const float*)d_in[14];
    const float* Wl3 = (const float*)d_in[15];
    const float* bl3 = (const float*)d_in[16];
    float* out = (float*)d_out;

    const int n = in_sizes[0] / 4;

    cudaFuncSetAttribute(reslinear_kernel,
                         cudaFuncAttributeMaxDynamicSharedMemorySize, SMEM_BYTES);

    const int grid = (n + NT - 1) / NT;
    reslinear_kernel<<<grid, NT, SMEM_BYTES>>>(
        x, fW, fB, bW, bB,
        Wn1, bn1, Wl1, bl1,
        Wn2, bn2, Wl2, bl2,
        Wn3, bn3, Wl3, bl3,
        out, n);
}

// round 11
// speedup vs baseline: 2.0651x; 1.2819x over previous
#include <cuda_runtime.h>
#include <cuda_fp16.h>
#include <cuda_bf16.h>

#define NT 512
typedef unsigned int u32;

// ---- shared memory layout (float-index offsets) ----
#define OFF_BF   0          // u32[84*9*32] = 24192 B-fragment words
#define OFF_BIAS 24192      // f32[84*24]  = 2016 (zero-padded to 24 cols)
#define OFF_H    26208      // f32[24][NT] front activations / reused for s
#define OFF_FR   (26208 + 24 * NT)            // f32[100]
#define OFF_BK   (26208 + 24 * NT + 100)      // f32[84]
#define SMEM_FLOATS (26208 + 24 * NT + 184)
#define SMEM_BYTES (SMEM_FLOATS * 4)          // 154720 @ NT=512

// pack two f32 -> f16x2 (lo = first arg -> .lo half)
__device__ __forceinline__ u32 packh2(float lo, float hi) {
    u32 r;
    asm("cvt.rn.f16x2.f32 %0, %1, %2;" : "=r"(r) : "f"(hi), "f"(lo));
    return r;
}

// half2 swish on a packed f16x2: hv = v/2 ; r = hv + hv*tanh(hv)
__device__ __forceinline__ u32 hswish2(u32 v) {
    u32 hv, t, r;
    asm("mul.rn.f16x2 %0, %1, %2;" : "=r"(hv) : "r"(v), "r"(0x38003800u));
    asm("tanh.approx.f16x2 %0, %1;" : "=r"(t) : "r"(hv));
    asm("fma.rn.f16x2 %0, %1, %2, %3;" : "=r"(r) : "r"(hv), "r"(t), "r"(hv));
    return r;
}
__device__ __forceinline__ u32 hadd2(u32 a, u32 b) {
    u32 r;
    asm("add.rn.f16x2 %0, %1, %2;" : "=r"(r) : "r"(a), "r"(b));
    return r;
}
__device__ __forceinline__ void h2f2(u32 v, float& lo, float& hi) {
    __half2 h = *reinterpret_cast<__half2*>(&v);
    float2 f = __half22float2(h);
    lo = f.x; hi = f.y;
}

// D(f32,m16n8) += A(f16,m16k16) * B(f16,k16n8)
__device__ __forceinline__ void mma16(float* d, u32 a0, u32 a1, u32 a2, u32 a3,
                                      u32 b0, u32 b1) {
    asm volatile(
        "mma.sync.aligned.m16n8k16.row.col.f32.f16.f16.f32 "
        "{%0,%1,%2,%3}, {%4,%5,%6,%7}, {%8,%9}, {%0,%1,%2,%3};"
        : "+f"(d[0]), "+f"(d[1]), "+f"(d[2]), "+f"(d[3])
        : "r"(a0), "r"(a1), "r"(a2), "r"(a3), "r"(b0), "r"(b1));
}
// D(f32,m16n8) += A(f16,m16k8) * B(f16,k8n8)
__device__ __forceinline__ void mma8(float* d, u32 a0, u32 a1, u32 b) {
    asm volatile(
        "mma.sync.aligned.m16n8k8.row.col.f32.f16.f16.f32 "
        "{%0,%1,%2,%3}, {%4,%5}, {%6}, {%0,%1,%2,%3};"
        : "+f"(d[0]), "+f"(d[1]), "+f"(d[2]), "+f"(d[3])
        : "r"(a0), "r"(a1), "r"(b));
}

// full 24x24 layer MMA for one tile: D[3][4] (bias pre-set) += A(frag) * B(L)
__device__ __forceinline__ void layer_mma(float D[3][4], const u32 a[3][2],
                                          const u32 bf[9]) {
#pragma unroll
    for (int ns = 0; ns < 3; ++ns) {
        mma16(D[ns], a[0][0], a[0][1], a[1][0], a[1][1], bf[0 + ns], bf[3 + ns]);
        mma8(D[ns], a[2][0], a[2][1], bf[6 + ns]);
    }
}

__global__ void __launch_bounds__(NT, 1)
reslinear_kernel(const float* __restrict__ x,
                 const float* __restrict__ fW, const float* __restrict__ fB,
                 const float* __restrict__ bW, const float* __restrict__ bB,
                 const float* __restrict__ Wn1, const float* __restrict__ bn1,
                 const float* __restrict__ Wl1, const float* __restrict__ bl1,
                 const float* __restrict__ Wn2, const float* __restrict__ bn2,
                 const float* __restrict__ Wl2, const float* __restrict__ bl2,
                 const float* __restrict__ Wn3, const float* __restrict__ bn3,
                 const float* __restrict__ Wl3, const float* __restrict__ bl3,
                 float* __restrict__ out, int n) {
    extern __shared__ float sm[];
    const int tid = threadIdx.x;
    u32* bfw = reinterpret_cast<u32*>(sm + OFF_BF);

    // ---- stage small params ----
    for (int w = tid; w < 80; w += NT) sm[OFF_FR + w] = fW[w];
    for (int w = tid; w < 20; w += NT) sm[OFF_FR + 80 + w] = fB[w];
    for (int w = tid; w < 80; w += NT) sm[OFF_BK + w] = bW[w];
    for (int w = tid; w < 4;  w += NT) sm[OFF_BK + 80 + w] = bB[w];

    // ---- pre-pack all 84 layer weights into mma B-fragment order (fp16) ----
    // B-frag word index: [L][t9 = ks*3+ns][lane]
    for (int w = tid; w < 24192; w += NT) {
        const int lane = w & 31;
        const int t9 = (w >> 5) % 9;
        const int L = w / 288;
        const int gb = L >> 2, j = L & 3;
        const float* W;
        if (gb < 16)      W = (j < 3) ? Wn1 + (gb * 3 + j) * 400 : Wl1 + gb * 400;
        else if (gb < 20) W = (j < 3) ? Wn2 + ((gb - 16) * 3 + j) * 400 : Wl2 + (gb - 16) * 400;
        else              W = (j < 3) ? Wn3 + j * 400 : Wl3;
        const int ks = t9 / 3, ns = t9 % 3;
        const int k0 = ks * 8 + (lane & 3) * 2;
        const int nn = ns * 8 + (lane >> 2);
        float lo = (k0     < 20 && nn < 20) ? W[k0 * 20 + nn]       : 0.f;
        float hi = (k0 + 1 < 20 && nn < 20) ? W[(k0 + 1) * 20 + nn] : 0.f;
        bfw[w] = packh2(lo, hi);
    }
    for (int w = tid; w < 2016; w += NT) {
        const int L = w / 24, nn = w % 24;
        const int gb = L >> 2, j = L & 3;
        const float* B;
        if (gb < 16)      B = (j < 3) ? bn1 + (gb * 3 + j) * 20 : bl1 + gb * 20;
        else if (gb < 20) B = (j < 3) ? bn2 + ((gb - 16) * 3 + j) * 20 : bl2 + (gb - 16) * 20;
        else              B = (j < 3) ? bn3 + j * 20 : bl3;
        sm[OFF_BIAS + w] = (nn < 20) ? B[nn] : 0.f;
    }
    __syncthreads();

    const int gidx = blockIdx.x * NT + tid;
    const int lidx = (gidx < n) ? gidx : (n - 1);

    // ---- front layer: h = x @ fW + fb into H[24][NT] (pad rows zero) ----
    {
        const float4 xv = reinterpret_cast<const float4*>(x)[lidx];
#pragma unroll
        for (int k = 0; k < 24; ++k) {
            float a = 0.f;
            if (k < 20) {
                a = sm[OFF_FR + 80 + k];
                a = fmaf(xv.x, sm[OFF_FR + 0 * 20 + k], a);
                a = fmaf(xv.y, sm[OFF_FR + 1 * 20 + k], a);
                a = fmaf(xv.z, sm[OFF_FR + 2 * 20 + k], a);
                a = fmaf(xv.w, sm[OFF_FR + 3 * 20 + k], a);
            }
            sm[OFF_H + k * NT + tid] = a;
        }
    }
    __syncthreads();

    const int lane = tid & 31, warp = tid >> 5;
    const int grp = lane >> 2, tq = lane & 3;
    const int p0 = warp * 32 + grp;        // tile0 base point (local)
    const int p1 = p0 + 16;                // tile1
    float* H = sm + OFF_H;
    const float* BIAS = sm + OFF_BIAS;

    float s[2][3][4];   // cross-chain accumulator, D-fragment layout (f32)

#pragma unroll
    for (int c = 0; c < 3; ++c) {
        // load h fragments from H (fragment-identity: A m16k8 == D m16n8 layout)
        u32 af[2][3][2];
#pragma unroll
        for (int t = 0; t < 2; ++t) {
            const int pb = t ? p1 : p0;
#pragma unroll
            for (int ks = 0; ks < 3; ++ks) {
                const int kk = ks * 8 + tq * 2;
                af[t][ks][0] = packh2(H[kk * NT + pb],     H[(kk + 1) * NT + pb]);
                af[t][ks][1] = packh2(H[kk * NT + pb + 8], H[(kk + 1) * NT + pb + 8]);
            }
        }
        const int b0 = (c == 0) ? 0 : (c == 1) ? 16 : 20;
        const int nb = (c == 0) ? 16 : (c == 1) ? 4 : 1;

        for (int blk = 0; blk < nb; ++blk) {
            const int Lb = (b0 + blk) * 4;
            u32 cur[2][3][2];
#pragma unroll
            for (int t = 0; t < 2; ++t)
#pragma unroll
                for (int ks = 0; ks < 3; ++ks) {
                    cur[t][ks][0] = af[t][ks][0];
                    cur[t][ks][1] = af[t][ks][1];
                }
            u32 o3h[2][3][2];   // layer-3 output, f16x2 fragments

            // ---- 3 net layers ----
#pragma unroll
            for (int j = 0; j < 3; ++j) {
                const int L = Lb + j;
                u32 bf[9];
#pragma unroll
                for (int t9 = 0; t9 < 9; ++t9) bf[t9] = bfw[(L * 9 + t9) * 32 + lane];
                float2 bp[3];
#pragma unroll
                for (int ns = 0; ns < 3; ++ns)
                    bp[ns] = *reinterpret_cast<const float2*>(BIAS + L * 24 + ns * 8 + tq * 2);
#pragma unroll
                for (int t = 0; t < 2; ++t) {
                    float D[3][4];
#pragma unroll
                    for (int ns = 0; ns < 3; ++ns) {
                        D[ns][0] = bp[ns].x; D[ns][1] = bp[ns].y;
                        D[ns][2] = bp[ns].x; D[ns][3] = bp[ns].y;
                    }
                    layer_mma(D, cur[t], bf);
#pragma unroll
                    for (int ns = 0; ns < 3; ++ns) {
                        u32 a = hswish2(packh2(D[ns][0], D[ns][1]));
                        u32 b = hswish2(packh2(D[ns][2], D[ns][3]));
                        if (j < 2) { cur[t][ns][0] = a; cur[t][ns][1] = b; }
                        else       { o3h[t][ns][0] = a; o3h[t][ns][1] = b; }
                    }
                }
            }

            // ---- shortcut + residual: h' = o3 + swish(h @ Wl + bl) ----
            {
                const int L = Lb + 3;
                u32 bf[9];
#pragma unroll
                for (int t9 = 0; t9 < 9; ++t9) bf[t9] = bfw[(L * 9 + t9) * 32 + lane];
                float2 bp[3];
#pragma unroll
                for (int ns = 0; ns < 3; ++ns)
                    bp[ns] = *reinterpret_cast<const float2*>(BIAS + L * 24 + ns * 8 + tq * 2);
#pragma unroll
                for (int t = 0; t < 2; ++t) {
                    float D[3][4];
#pragma unroll
                    for (int ns = 0; ns < 3; ++ns) {
                        D[ns][0] = bp[ns].x; D[ns][1] = bp[ns].y;
                        D[ns][2] = bp[ns].x; D[ns][3] = bp[ns].y;
                    }
                    layer_mma(D, af[t], bf);
#pragma unroll
                    for (int ns = 0; ns < 3; ++ns) {
                        u32 hp0 = hadd2(o3h[t][ns][0], hswish2(packh2(D[ns][0], D[ns][1])));
                        u32 hp1 = hadd2(o3h[t][ns][1], hswish2(packh2(D[ns][2], D[ns][3])));
                        af[t][ns][0] = hp0;
                        af[t][ns][1] = hp1;
                        if (blk == nb - 1) {
                            float f0, f1, f2, f3;
                            h2f2(hp0, f0, f1);
                            h2f2(hp1, f2, f3);
                            if (c == 0) {
                                s[t][ns][0] = f0; s[t][ns][1] = f1;
                                s[t][ns][2] = f2; s[t][ns][3] = f3;
                            } else {
                                s[t][ns][0] += f0; s[t][ns][1] += f1;
                                s[t][ns][2] += f2; s[t][ns][3] += f3;
                            }
                        }
                    }
                }
            }
        }
    }

    // ---- back layer: scatter s (D-layout) into H, then per-thread dot ----
#pragma unroll
    for (int t = 0; t < 2; ++t) {
        const int pb = t ? p1 : p0;
#pragma unroll
        for (int ns = 0; ns < 3; ++ns) {
            const int col = ns * 8 + tq * 2;
            H[col * NT + pb]           = s[t][ns][0];
            H[(col + 1) * NT + pb]     = s[t][ns][1];
            H[col * NT + pb + 8]       = s[t][ns][2];
            H[(col + 1) * NT + pb + 8] = s[t][ns][3];
        }
    }
    __syncwarp();

    float4 y;
    y.x = sm[OFF_BK + 80];
    y.y = sm[OFF_BK + 81];
    y.z = sm[OFF_BK + 82];
    y.w = sm[OFF_BK + 83];
#pragma unroll
    for (int k = 0; k < 20; ++k) {
        const float sk = H[k * NT + tid];
        y.x = fmaf(sk, sm[OFF_BK + k * 4 + 0], y.x);
        y.y = fmaf(sk, sm[OFF_BK + k * 4 + 1], y.y);
        y.z = fmaf(sk, sm[OFF_BK + k * 4 + 2], y.z);
        y.w = fmaf(sk, sm[OFF_BK + k * 4 + 3], y.w);
    }
    if (gidx < n) reinterpret_cast<float4*>(out)[gidx] = y;
}

extern "C" void kernel_launch(void* const* d_in, const int* in_sizes, int n_in,
                              void* d_out, int out_size) {
    const float* x   = (const float*)d_in[0];
    const float* fW  = (const float*)d_in[1];
    const float* fB  = (const float*)d_in[2];
    const float* bW  = (const float*)d_in[3];
    const float* bB  = (const float*)d_in[4];
    const float* Wn1 = (const float*)d_in[5];
    const float* bn1 = (const float*)d_in[6];
    const float* Wl1 = (const float*)d_in[7];
    const float* bl1 = (const float*)d_in[8];
    const float* Wn2 = (const float*)d_in[9];
    const float* bn2 = (const float*)d_in[10];
    const float* Wl2 = (const float*)d_in[11];
    const float* bl2 = (const float*)d_in[12];
    const float* Wn3 = (const float*)d_in[13];
    const float* bn3 = (const float*)d_in[14];
    const float* Wl3 = (const float*)d_in[15];
    const float* bl3 = (const float*)d_in[16];
    float* out = (float*)d_out;

    const int n = in_sizes[0] / 4;

    cudaFuncSetAttribute(reslinear_kernel,
                         cudaFuncAttributeMaxDynamicSharedMemorySize, SMEM_BYTES);

    const int grid = (n + NT - 1) / NT;
    reslinear_kernel<<<grid, NT, SMEM_BYTES>>>(
        x, fW, fB, bW, bB,
        Wn1, bn1, Wl1, bl1,
        Wn2, bn2, Wl2, bl2,
        Wn3, bn3, Wl3, bl3,
        out, n);
}

// round 12
// speedup vs baseline: 2.1363x; 1.0345x over previous
#include <cuda_runtime.h>
#include <cuda_fp16.h>
#include <cuda_bf16.h>

#define NT 512
typedef unsigned int u32;

// ---- shared memory layout (float-index offsets) ----
#define OFF_BF   0          // u32[84*9*32] = 24192 B-fragment words
#define OFF_BIAS 24192      // u32[84*12]  = 1008 bias f16x2 (per L, ns, tq)
#define OFF_H    25200      // f32[24][NT] front activations / reused for s
#define OFF_FR   (25200 + 24 * NT)            // f32[100]
#define OFF_BK   (25200 + 24 * NT + 100)      // f32[84]
#define SMEM_FLOATS (25200 + 24 * NT + 184)
#define SMEM_BYTES (SMEM_FLOATS * 4)          // 150688 @ NT=512

// pack two f32 -> f16x2 (lo = first arg -> .lo half)
__device__ __forceinline__ u32 packh2(float lo, float hi) {
    u32 r;
    asm("cvt.rn.f16x2.f32 %0, %1, %2;" : "=r"(r) : "f"(hi), "f"(lo));
    return r;
}

// half2 swish on a packed f16x2: hv = v/2 ; r = hv + hv*tanh(hv)
__device__ __forceinline__ u32 hswish2(u32 v) {
    u32 hv, t, r;
    asm("mul.rn.f16x2 %0, %1, %2;" : "=r"(hv) : "r"(v), "r"(0x38003800u));
    asm("tanh.approx.f16x2 %0, %1;" : "=r"(t) : "r"(hv));
    asm("fma.rn.f16x2 %0, %1, %2, %3;" : "=r"(r) : "r"(hv), "r"(t), "r"(hv));
    return r;
}
__device__ __forceinline__ u32 hadd2(u32 a, u32 b) {
    u32 r;
    asm("add.rn.f16x2 %0, %1, %2;" : "=r"(r) : "r"(a), "r"(b));
    return r;
}
__device__ __forceinline__ void h2f2(u32 v, float& lo, float& hi) {
    __half2 h = *reinterpret_cast<__half2*>(&v);
    float2 f = __half22float2(h);
    lo = f.x; hi = f.y;
}

// f16-accum MMA: D(f16x2 x2, m16n8) = A(m16k16) * B(k16n8) + C  (C may differ from D)
__device__ __forceinline__ void mma16h_init(u32& d0, u32& d1,
                                            u32 a0, u32 a1, u32 a2, u32 a3,
                                            u32 b0, u32 b1, u32 c0, u32 c1) {
    asm volatile(
        "mma.sync.aligned.m16n8k16.row.col.f16.f16.f16.f16 "
        "{%0,%1}, {%2,%3,%4,%5}, {%6,%7}, {%8,%9};"
        : "=r"(d0), "=r"(d1)
        : "r"(a0), "r"(a1), "r"(a2), "r"(a3), "r"(b0), "r"(b1), "r"(c0), "r"(c1));
}
// f16-accum MMA accumulate-in-place: D += A(m16k8) * B(k8n8)
__device__ __forceinline__ void mma8h(u32& d0, u32& d1, u32 a0, u32 a1, u32 b) {
    asm volatile(
        "mma.sync.aligned.m16n8k8.row.col.f16.f16.f16.f16 "
        "{%0,%1}, {%2,%3}, {%4}, {%0,%1};"
        : "+r"(d0), "+r"(d1)
        : "r"(a0), "r"(a1), "r"(b));
}

// full 24x24 layer for one tile: Dh[3][2] = A * B(L) + bias
__device__ __forceinline__ void layer_mma_h(u32 Dh[3][2], const u32 a[3][2],
                                            const u32 bf[9], const u32 bh[3]) {
#pragma unroll
    for (int ns = 0; ns < 3; ++ns) {
        mma16h_init(Dh[ns][0], Dh[ns][1],
                    a[0][0], a[0][1], a[1][0], a[1][1],
                    bf[0 + ns], bf[3 + ns], bh[ns], bh[ns]);
        mma8h(Dh[ns][0], Dh[ns][1], a[2][0], a[2][1], bf[6 + ns]);
    }
}

__global__ void __launch_bounds__(NT, 1)
reslinear_kernel(const float* __restrict__ x,
                 const float* __restrict__ fW, const float* __restrict__ fB,
                 const float* __restrict__ bW, const float* __restrict__ bB,
                 const float* __restrict__ Wn1, const float* __restrict__ bn1,
                 const float* __restrict__ Wl1, const float* __restrict__ bl1,
                 const float* __restrict__ Wn2, const float* __restrict__ bn2,
                 const float* __restrict__ Wl2, const float* __restrict__ bl2,
                 const float* __restrict__ Wn3, const float* __restrict__ bn3,
                 const float* __restrict__ Wl3, const float* __restrict__ bl3,
                 float* __restrict__ out, int n) {
    extern __shared__ float sm[];
    const int tid = threadIdx.x;
    u32* bfw = reinterpret_cast<u32*>(sm + OFF_BF);
    u32* bhs = reinterpret_cast<u32*>(sm + OFF_BIAS);

    // ---- stage small params ----
    for (int w = tid; w < 80; w += NT) sm[OFF_FR + w] = fW[w];
    for (int w = tid; w < 20; w += NT) sm[OFF_FR + 80 + w] = fB[w];
    for (int w = tid; w < 80; w += NT) sm[OFF_BK + w] = bW[w];
    for (int w = tid; w < 4;  w += NT) sm[OFF_BK + 80 + w] = bB[w];

    // ---- pre-pack all 84 layer weights into mma B-fragment order (fp16) ----
    for (int w = tid; w < 24192; w += NT) {
        const int lane = w & 31;
        const int t9 = (w >> 5) % 9;
        const int L = w / 288;
        const int gb = L >> 2, j = L & 3;
        const float* W;
        if (gb < 16)      W = (j < 3) ? Wn1 + (gb * 3 + j) * 400 : Wl1 + gb * 400;
        else if (gb < 20) W = (j < 3) ? Wn2 + ((gb - 16) * 3 + j) * 400 : Wl2 + (gb - 16) * 400;
        else              W = (j < 3) ? Wn3 + j * 400 : Wl3;
        const int ks = t9 / 3, ns = t9 % 3;
        const int k0 = ks * 8 + (lane & 3) * 2;
        const int nn = ns * 8 + (lane >> 2);
        float lo = (k0     < 20 && nn < 20) ? W[k0 * 20 + nn]       : 0.f;
        float hi = (k0 + 1 < 20 && nn < 20) ? W[(k0 + 1) * 20 + nn] : 0.f;
        bfw[w] = packh2(lo, hi);
    }
    // ---- bias as f16x2, indexed [L][ns][tq] -> cols (ns*8+tq*2, +1) ----
    for (int w = tid; w < 1008; w += NT) {
        const int L = w / 12, r = w % 12;
        const int ns = r >> 2, tq = r & 3;
        const int gb = L >> 2, j = L & 3;
        const float* B;
        if (gb < 16)      B = (j < 3) ? bn1 + (gb * 3 + j) * 20 : bl1 + gb * 20;
        else if (gb < 20) B = (j < 3) ? bn2 + ((gb - 16) * 3 + j) * 20 : bl2 + (gb - 16) * 20;
        else              B = (j < 3) ? bn3 + j * 20 : bl3;
        const int c0 = ns * 8 + tq * 2;
        bhs[w] = packh2(c0 < 20 ? B[c0] : 0.f, c0 + 1 < 20 ? B[c0 + 1] : 0.f);
    }
    __syncthreads();

    const int gidx = blockIdx.x * NT + tid;
    const int lidx = (gidx < n) ? gidx : (n - 1);

    // ---- front layer: h = x @ fW + fb into H[24][NT] (pad rows zero) ----
    {
        const float4 xv = reinterpret_cast<const float4*>(x)[lidx];
#pragma unroll
        for (int k = 0; k < 24; ++k) {
            float a = 0.f;
            if (k < 20) {
                a = sm[OFF_FR + 80 + k];
                a = fmaf(xv.x, sm[OFF_FR + 0 * 20 + k], a);
                a = fmaf(xv.y, sm[OFF_FR + 1 * 20 + k], a);
                a = fmaf(xv.z, sm[OFF_FR + 2 * 20 + k], a);
                a = fmaf(xv.w, sm[OFF_FR + 3 * 20 + k], a);
            }
            sm[OFF_H + k * NT + tid] = a;
        }
    }
    __syncthreads();

    const int lane = tid & 31, warp = tid >> 5;
    const int grp = lane >> 2, tq = lane & 3;
    const int p0 = warp * 32 + grp;        // tile0 base point (local)
    const int p1 = p0 + 16;                // tile1
    float* H = sm + OFF_H;

    float s[2][3][4];   // cross-chain accumulator (f32), D-fragment layout

#pragma unroll
    for (int c = 0; c < 3; ++c) {
        // load h fragments from H (fragment-identity: f16 D m16n8 == A m16k8)
        u32 af[2][3][2];
#pragma unroll
        for (int t = 0; t < 2; ++t) {
            const int pb = t ? p1 : p0;
#pragma unroll
            for (int ks = 0; ks < 3; ++ks) {
                const int kk = ks * 8 + tq * 2;
                af[t][ks][0] = packh2(H[kk * NT + pb],     H[(kk + 1) * NT + pb]);
                af[t][ks][1] = packh2(H[kk * NT + pb + 8], H[(kk + 1) * NT + pb + 8]);
            }
        }
        const int b0 = (c == 0) ? 0 : (c == 1) ? 16 : 20;
        const int nb = (c == 0) ? 16 : (c == 1) ? 4 : 1;

        for (int blk = 0; blk < nb; ++blk) {
            const int Lb = (b0 + blk) * 4;
            u32 cur[2][3][2];
#pragma unroll
            for (int t = 0; t < 2; ++t)
#pragma unroll
                for (int ks = 0; ks < 3; ++ks) {
                    cur[t][ks][0] = af[t][ks][0];
                    cur[t][ks][1] = af[t][ks][1];
                }
            u32 o3h[2][3][2];   // layer-3 output, f16x2 fragments

            // ---- 3 net layers ----
#pragma unroll
            for (int j = 0; j < 3; ++j) {
                const int L = Lb + j;
                u32 bf[9];
#pragma unroll
                for (int t9 = 0; t9 < 9; ++t9) bf[t9] = bfw[(L * 9 + t9) * 32 + lane];
                u32 bh[3];
#pragma unroll
                for (int ns = 0; ns < 3; ++ns) bh[ns] = bhs[L * 12 + ns * 4 + tq];
#pragma unroll
                for (int t = 0; t < 2; ++t) {
                    u32 Dh[3][2];
                    layer_mma_h(Dh, cur[t], bf, bh);
#pragma unroll
                    for (int ns = 0; ns < 3; ++ns) {
                        u32 a = hswish2(Dh[ns][0]);
                        u32 b = hswish2(Dh[ns][1]);
                        if (j < 2) { cur[t][ns][0] = a; cur[t][ns][1] = b; }
                        else       { o3h[t][ns][0] = a; o3h[t][ns][1] = b; }
                    }
                }
            }

            // ---- shortcut + residual: h' = o3 + swish(h @ Wl + bl) ----
            {
                const int L = Lb + 3;
                u32 bf[9];
#pragma unroll
                for (int t9 = 0; t9 < 9; ++t9) bf[t9] = bfw[(L * 9 + t9) * 32 + lane];
                u32 bh[3];
#pragma unroll
                for (int ns = 0; ns < 3; ++ns) bh[ns] = bhs[L * 12 + ns * 4 + tq];
#pragma unroll
                for (int t = 0; t < 2; ++t) {
                    u32 Dh[3][2];
                    layer_mma_h(Dh, af[t], bf, bh);
#pragma unroll
                    for (int ns = 0; ns < 3; ++ns) {
                        u32 hp0 = hadd2(o3h[t][ns][0], hswish2(Dh[ns][0]));
                        u32 hp1 = hadd2(o3h[t][ns][1], hswish2(Dh[ns][1]));
                        af[t][ns][0] = hp0;
                        af[t][ns][1] = hp1;
                        if (blk == nb - 1) {
                            float f0, f1, f2, f3;
                            h2f2(hp0, f0, f1);
                            h2f2(hp1, f2, f3);
                            if (c == 0) {
                                s[t][ns][0] = f0; s[t][ns][1] = f1;
                                s[t][ns][2] = f2; s[t][ns][3] = f3;
                            } else {
                                s[t][ns][0] += f0; s[t][ns][1] += f1;
                                s[t][ns][2] += f2; s[t][ns][3] += f3;
                            }
                        }
                    }
                }
            }
        }
    }

    // ---- back layer: scatter s (D-layout) into H, then per-thread dot ----
    // f16 D fragment: reg0 = (row grp, cols tq*2,+1); reg1 = (row grp+8, same)
#pragma unroll
    for (int t = 0; t < 2; ++t) {
        const int pb = t ? p1 : p0;
#pragma unroll
        for (int ns = 0; ns < 3; ++ns) {
            const int col = ns * 8 + tq * 2;
            H[col * NT + pb]           = s[t][ns][0];
            H[(col + 1) * NT + pb]     = s[t][ns][1];
            H[col * NT + pb + 8]       = s[t][ns][2];
            H[(col + 1) * NT + pb + 8] = s[t][ns][3];
        }
    }
    __syncwarp();

    float4 y;
    y.x = sm[OFF_BK + 80];
    y.y = sm[OFF_BK + 81];
    y.z = sm[OFF_BK + 82];
    y.w = sm[OFF_BK + 83];
#pragma unroll
    for (int k = 0; k < 20; ++k) {
        const float sk = H[k * NT + tid];
        y.x = fmaf(sk, sm[OFF_BK + k * 4 + 0], y.x);
        y.y = fmaf(sk, sm[OFF_BK + k * 4 + 1], y.y);
        y.z = fmaf(sk, sm[OFF_BK + k * 4 + 2], y.z);
        y.w = fmaf(sk, sm[OFF_BK + k * 4 + 3], y.w);
    }
    if (gidx < n) reinterpret_cast<float4*>(out)[gidx] = y;
}

extern "C" void kernel_launch(void* const* d_in, const int* in_sizes, int n_in,
                              void* d_out, int out_size) {
    const float* x   = (const float*)d_in[0];
    const float* fW  = (const float*)d_in[1];
    const float* fB  = (const float*)d_in[2];
    const float* bW  = (const float*)d_in[3];
    const float* bB  = (const float*)d_in[4];
    const float* Wn1 = (const float*)d_in[5];
    const float* bn1 = (const float*)d_in[6];
    const float* Wl1 = (const float*)d_in[7];
    const float* bl1 = (const float*)d_in[8];
    const float* Wn2 = (const float*)d_in[9];
    const float* bn2 = (const float*)d_in[10];
    const float* Wl2 = (const float*)d_in[11];
    const float* bl2 = (const float*)d_in[12];
    const float* Wn3 = (const float*)d_in[13];
    const float* bn3 = (const float*)d_in[14];
    const float* Wl3 = (const float*)d_in[15];
    const float* bl3 = (const float*)d_in[16];
    float* out = (float*)d_out;

    const int n = in_sizes[0] / 4;

    cudaFuncSetAttribute(reslinear_kernel,
                         cudaFuncAttributeMaxDynamicSharedMemorySize, SMEM_BYTES);

    const int grid = (n + NT - 1) / NT;
    reslinear_kernel<<<grid, NT, SMEM_BYTES>>>(
        x, fW, fB, bW, bB,
        Wn1, bn1, Wl1, bl1,
        Wn2, bn2, Wl2, bl2,
        Wn3, bn3, Wl3, bl3,
        out, n);
}